// round 2
// baseline (speedup 1.0000x reference)
#include <cuda_runtime.h>
#include <math.h>

#define DIMQK 128
#define MF 256
#define RPB 64
#define NTHREADS 256

// ---------------- device scratch (allocation-free rule: device globals) ---------
static __device__ unsigned g_max_u;          // monotone-key encoded global max of U_K
static __device__ float    g_maxval;         // decoded gmax
static __device__ float    g_sumKraw[MF];    // sum_n exp(U_K - h)   (pre gmax scaling)
static __device__ float    g_sumK[MF];       // final sum_n Kp

__device__ __forceinline__ unsigned f2u(float f) {
    unsigned b = __float_as_uint(f);
    return (b & 0x80000000u) ? ~b : (b | 0x80000000u);
}
__device__ __forceinline__ float u2f(unsigned u) {
    return (u & 0x80000000u) ? __uint_as_float(u ^ 0x80000000u)
                             : __uint_as_float(~u);
}

__global__ void sp_init() {
    if (threadIdx.x == 0) g_max_u = 0u;   // key(-inf) > 0, so 0 is below everything
    g_sumKraw[threadIdx.x] = 0.f;
}

// 64x256 fp32 GEMM tile: A[64][128] (smem, row-major), om[128][256] (smem).
// Thread (ty,tx): rows ty*8..ty*8+7, cols tx + 32*j (j<8). acc[i][j].
__device__ __forceinline__ void gemm64x256(const float* __restrict__ A,
                                           const float* __restrict__ om,
                                           int ty, int tx, float acc[8][8]) {
#pragma unroll
    for (int i = 0; i < 8; i++)
#pragma unroll
        for (int j = 0; j < 8; j++) acc[i][j] = 0.f;

    const float* Ab = A + ty * 8 * DIMQK;
#pragma unroll 2
    for (int k = 0; k < DIMQK; k += 4) {
        float4 av[8];
#pragma unroll
        for (int i = 0; i < 8; i++)
            av[i] = *reinterpret_cast<const float4*>(Ab + i * DIMQK + k);
#pragma unroll
        for (int kk = 0; kk < 4; kk++) {
            float bv[8];
#pragma unroll
            for (int j = 0; j < 8; j++) bv[j] = om[(k + kk) * MF + tx + 32 * j];
#pragma unroll
            for (int i = 0; i < 8; i++) {
                const float a = (kk == 0) ? av[i].x : (kk == 1) ? av[i].y
                              : (kk == 2) ? av[i].z : av[i].w;
#pragma unroll
                for (int j = 0; j < 8; j++)
                    acc[i][j] = fmaf(a, bv[j], acc[i][j]);
            }
        }
    }
}

__device__ __forceinline__ void load_omega(const float* __restrict__ omg,
                                           float* __restrict__ om, int tid) {
    const float invd4 = 0.2973017787506803f;  // 128^(-1/4)
    for (int i = tid; i < DIMQK * MF / 4; i += NTHREADS) {
        float4 v = reinterpret_cast<const float4*>(omg)[i];
        v.x *= invd4; v.y *= invd4; v.z *= invd4; v.w *= invd4;
        reinterpret_cast<float4*>(om)[i] = v;
    }
}

__device__ __forceinline__ void load_rows(const float* __restrict__ src,
                                          float* __restrict__ A, size_t row0, int tid) {
    const float4* g = reinterpret_cast<const float4*>(src + row0 * DIMQK);
    for (int i = tid; i < RPB * DIMQK / 4; i += NTHREADS)
        reinterpret_cast<float4*>(A)[i] = g[i];
}

__device__ __forceinline__ void compute_h(const float* __restrict__ A,
                                          float* __restrict__ hsh, int tid) {
    if (tid < RPB) {
        const float* ar = A + tid * DIMQK;
        float s = 0.f;
#pragma unroll
        for (int k = 0; k < DIMQK; k++) s = fmaf(ar[k], ar[k], s);
        hsh[tid] = s * 0.04419417382415922f;  // 1/(2*sqrt(128))
    }
}

// ------------- pass 1: U_K = (K/d^.25)@omega -> global max + raw column sums ----
__global__ void __launch_bounds__(NTHREADS, 1)
sp_kpass(const float* __restrict__ Kin, const float* __restrict__ omg) {
    extern __shared__ float sh[];
    float* om  = sh;                    // 32768
    float* A   = om + DIMQK * MF;       // 8192
    float* hsh = A + RPB * DIMQK;       // 64
    __shared__ float warpmax[8];

    const int tid = threadIdx.x;
    load_omega(omg, om, tid);
    const size_t row0 = (size_t)blockIdx.x * RPB;
    load_rows(Kin, A, row0, tid);
    __syncthreads();
    compute_h(A, hsh, tid);
    __syncthreads();

    const int ty = tid >> 5, tx = tid & 31;
    float acc[8][8];
    gemm64x256(A, om, ty, tx, acc);

    // epilogue: block max + per-column sums of exp(U - h)
    float bm = -INFINITY;
    float cs[8];
#pragma unroll
    for (int j = 0; j < 8; j++) cs[j] = 0.f;
#pragma unroll
    for (int i = 0; i < 8; i++) {
        const float h = hsh[ty * 8 + i];
#pragma unroll
        for (int j = 0; j < 8; j++) {
            const float u = acc[i][j];
            bm = fmaxf(bm, u);
            cs[j] += expf(u - h);
        }
    }
#pragma unroll
    for (int o = 16; o; o >>= 1)
        bm = fmaxf(bm, __shfl_xor_sync(0xffffffffu, bm, o));
    if (tx == 0) warpmax[ty] = bm;

    __syncthreads();  // all GEMM reads of A done -> reuse A as reduction buffer
    float* red = A;   // 8*256 floats needed, 8192 available
#pragma unroll
    for (int j = 0; j < 8; j++) red[ty * MF + tx + 32 * j] = cs[j];
    __syncthreads();

    if (tid < MF) {
        float s = 0.f;
#pragma unroll
        for (int w = 0; w < 8; w++) s += red[w * MF + tid];
        atomicAdd(&g_sumKraw[tid], s);
    }
    if (tid == 0) {
        float m = warpmax[0];
#pragma unroll
        for (int w = 1; w < 8; w++) m = fmaxf(m, warpmax[w]);
        atomicMax(&g_max_u, f2u(m));
    }
}

// ------------- tiny finalize: rescale raw sums by exp(-gmax), add N*eps ---------
__global__ void sp_finalize(float neps) {
    const float gmax = u2f(g_max_u);
    if (threadIdx.x == 0) g_maxval = gmax;
    g_sumK[threadIdx.x] =
        (g_sumKraw[threadIdx.x] * expf(-gmax) + neps) * 0.0625f;  // /sqrt(256)
}

// ------------- pass 2: recompute U_K -> Kp; U_Q -> Qp; w, norm; scale V ---------
__global__ void __launch_bounds__(NTHREADS, 1)
sp_final(const float* __restrict__ Q, const float* __restrict__ Kin,
         const float* __restrict__ V, const float* __restrict__ omg,
         float* __restrict__ out) {
    extern __shared__ float sh[];
    float* om  = sh;                    // 32768
    float* A   = om + DIMQK * MF;       // 8192
    float* Kp  = A + RPB * DIMQK;       // 16384
    float* hsh = Kp + RPB * MF;         // 64
    float* sK  = hsh + RPB;             // 256
    float* wsh = sK + MF;               // 64
    float* nsh = wsh + RPB;             // 64

    const int tid = threadIdx.x;
    load_omega(omg, om, tid);
    if (tid < MF) sK[tid] = g_sumK[tid];
    const float gmax = g_maxval;
    const size_t row0 = (size_t)blockIdx.x * RPB;
    const int ty = tid >> 5, tx = tid & 31;
    float acc[8][8];

    // ---- K phase ----
    load_rows(Kin, A, row0, tid);
    __syncthreads();
    compute_h(A, hsh, tid);
    __syncthreads();
    gemm64x256(A, om, ty, tx, acc);
#pragma unroll
    for (int i = 0; i < 8; i++) {
        const float h = hsh[ty * 8 + i];
#pragma unroll
        for (int j = 0; j < 8; j++)
            Kp[(ty * 8 + i) * MF + tx + 32 * j] =
                (expf(acc[i][j] - h - gmax) + 1e-4f) * 0.0625f;
    }
    __syncthreads();

    // ---- Q phase ----
    load_rows(Q, A, row0, tid);
    __syncthreads();
    compute_h(A, hsh, tid);
    __syncthreads();
    gemm64x256(A, om, ty, tx, acc);

#pragma unroll
    for (int i = 0; i < 8; i++) {
        const int row = ty * 8 + i;
        float rm = acc[i][0];
#pragma unroll
        for (int j = 1; j < 8; j++) rm = fmaxf(rm, acc[i][j]);
#pragma unroll
        for (int o = 16; o; o >>= 1)
            rm = fmaxf(rm, __shfl_xor_sync(0xffffffffu, rm, o));
        const float hq = hsh[row];
        float w = 0.f, nm = 0.f;
#pragma unroll
        for (int j = 0; j < 8; j++) {
            const float qp = (expf(acc[i][j] - hq - rm) + 1e-4f) * 0.0625f;
            w  = fmaf(qp, Kp[row * MF + tx + 32 * j], w);
            nm = fmaf(qp, sK[tx + 32 * j], nm);
        }
#pragma unroll
        for (int o = 16; o; o >>= 1) {
            w  += __shfl_xor_sync(0xffffffffu, w, o);
            nm += __shfl_xor_sync(0xffffffffu, nm, o);
        }
        if (tx == 0) { wsh[row] = w; nsh[row] = nm + 1e-8f; }
    }
    __syncthreads();

    // ---- output: out = (w/norm) * V ----
    const float4* Vg = reinterpret_cast<const float4*>(V + row0 * DIMQK);
    float4*       Og = reinterpret_cast<float4*>(out + row0 * DIMQK);
    for (int i = tid; i < RPB * DIMQK / 4; i += NTHREADS) {
        const int r = i >> 5;  // 32 float4 per row of 128
        const float sc = wsh[r] / nsh[r];
        float4 v = Vg[i];
        v.x *= sc; v.y *= sc; v.z *= sc; v.w *= sc;
        Og[i] = v;
    }
}

// --------------------------------- host -----------------------------------------
extern "C" void kernel_launch(void* const* d_in, const int* in_sizes, int n_in,
                              void* d_out, int out_size) {
    const float* Q   = (const float*)d_in[0];
    const float* K   = (const float*)d_in[1];
    const float* V   = (const float*)d_in[2];
    const float* omg = (const float*)d_in[3];
    float* out = (float*)d_out;

    const int N    = in_sizes[0] / DIMQK;
    const int nblk = N / RPB;

    const size_t smemA = (size_t)(DIMQK * MF + RPB * DIMQK + RPB) * sizeof(float);
    const size_t smemF = (size_t)(DIMQK * MF + RPB * DIMQK + RPB * MF + RPB + MF +
                                  RPB + RPB) * sizeof(float);
    cudaFuncSetAttribute(sp_kpass, cudaFuncAttributeMaxDynamicSharedMemorySize,
                         (int)smemA);
    cudaFuncSetAttribute(sp_final, cudaFuncAttributeMaxDynamicSharedMemorySize,
                         (int)smemF);

    sp_init<<<1, MF>>>();
    sp_kpass<<<nblk, NTHREADS, smemA>>>(K, omg);
    sp_finalize<<<1, MF>>>((float)N * 1e-4f);
    sp_final<<<nblk, NTHREADS, smemF>>>(Q, K, V, omg, out);
}

// round 4
// speedup vs baseline: 1.4893x; 1.4893x over previous
#include <cuda_runtime.h>
#include <math.h>
#include <stdint.h>

#define NT     512
#define MTILE  128
#define NF     256
#define KD     128

#define INVD4  0.2973017787506803f    // 128^(-1/4)
#define HC     0.04419417382415922f   // 1/(2*sqrt(128))

#define BFF_F  32768                  // B fragments: 128 KB
#define AFF_F  16384                  // A fragments: 64 KB

// ---------------- globals -------------------------------------------------------
static __device__ unsigned g_max_u;
static __device__ float    g_maxval;
static __device__ float    g_sumKraw[NF];
static __device__ float    g_sumK[NF];

__device__ __forceinline__ unsigned f2u(float f) {
    unsigned b = __float_as_uint(f);
    return (b & 0x80000000u) ? ~b : (b | 0x80000000u);
}
__device__ __forceinline__ float u2f(unsigned u) {
    return (u & 0x80000000u) ? __uint_as_float(u ^ 0x80000000u) : __uint_as_float(~u);
}

__global__ void sp_init() {
    if (threadIdx.x == 0) g_max_u = 0u;
    g_sumKraw[threadIdx.x] = 0.f;
}
__global__ void sp_finalize(float neps) {
    const float gmax = u2f(g_max_u);
    if (threadIdx.x == 0) g_maxval = gmax;
    g_sumK[threadIdx.x] = (g_sumKraw[threadIdx.x] * expf(-gmax) + neps) * 0.0625f;
}

// ---------------- tf32 mma machinery --------------------------------------------
__device__ __forceinline__ float to_tf32(float x) {
    uint32_t u;
    asm("cvt.rna.tf32.f32 %0, %1;" : "=r"(u) : "f"(x));
    return __uint_as_float(u);
}
__device__ __forceinline__ void mma_tf32(float* d, const float4& a, float b0, float b1) {
    asm volatile(
        "mma.sync.aligned.m16n8k8.row.col.f32.tf32.tf32.f32 "
        "{%0,%1,%2,%3}, {%4,%5,%6,%7}, {%8,%9}, {%0,%1,%2,%3};\n"
        : "+f"(d[0]), "+f"(d[1]), "+f"(d[2]), "+f"(d[3])
        : "r"(__float_as_uint(a.x)), "r"(__float_as_uint(a.y)),
          "r"(__float_as_uint(a.z)), "r"(__float_as_uint(a.w)),
          "r"(__float_as_uint(b0)), "r"(__float_as_uint(b1)));
}

// fragment-major A store: row r (0..127), col k (0..127)
__device__ __forceinline__ void store_Afrag(float* Aff, int r, int k, float val) {
    const int mi = r >> 4, rlo = r & 15, ks = k >> 3;
    const int lane = ((rlo & 7) << 2) | (k & 3);
    const int reg  = (rlo >> 3) | (((k >> 2) & 1) << 1);
    Aff[((mi * 16 + ks) * 32 + lane) * 4 + reg] = val;
}

// load omega (scaled, tf32) into fragment-major B
__device__ __forceinline__ void load_B(const float* __restrict__ omg, float* Bff, int tid) {
    for (int i = tid; i < KD * NF / 4; i += NT) {
        const int k = i >> 6;
        const int n0 = (i & 63) << 2;
        float4 v = reinterpret_cast<const float4*>(omg)[i];
        float vals[4] = {v.x, v.y, v.z, v.w};
#pragma unroll
        for (int t = 0; t < 4; t++) {
            const int n = n0 + t;
            const float val = to_tf32(vals[t] * INVD4);
            const int nt = n >> 3, np = nt >> 1, ks = k >> 3;
            const int lane = ((n & 7) << 2) | (k & 3);
            const int slot = ((nt & 1) << 1) | ((k >> 2) & 1);
            Bff[((np * 16 + ks) * 32 + lane) * 4 + slot] = val;
        }
    }
}

// load X tile into fragment-major A (+optional |x|^2 accumulation, fp32 source)
__device__ __forceinline__ void load_A(const float* __restrict__ X, size_t row0,
                                       float* Aff, float* hraw, int tid, bool do_h) {
    const float4* g = reinterpret_cast<const float4*>(X + row0 * KD);
    for (int i = tid; i < MTILE * KD / 4; i += NT) {
        const int r = i >> 5, k0 = (i & 31) << 2;
        float4 v = g[i];
        if (do_h) atomicAdd(&hraw[r], v.x * v.x + v.y * v.y + v.z * v.z + v.w * v.w);
        store_Afrag(Aff, r, k0 + 0, to_tf32(v.x));
        store_Afrag(Aff, r, k0 + 1, to_tf32(v.y));
        store_Afrag(Aff, r, k0 + 2, to_tf32(v.z));
        store_Afrag(Aff, r, k0 + 3, to_tf32(v.w));
    }
}
// load (Q+K) tile
__device__ __forceinline__ void load_S(const float* __restrict__ Qg,
                                       const float* __restrict__ Kg, size_t row0,
                                       float* Aff, int tid) {
    const float4* gq = reinterpret_cast<const float4*>(Qg + row0 * KD);
    const float4* gk = reinterpret_cast<const float4*>(Kg + row0 * KD);
    for (int i = tid; i < MTILE * KD / 4; i += NT) {
        const int r = i >> 5, k0 = (i & 31) << 2;
        float4 a = gq[i], b = gk[i];
        store_Afrag(Aff, r, k0 + 0, to_tf32(a.x + b.x));
        store_Afrag(Aff, r, k0 + 1, to_tf32(a.y + b.y));
        store_Afrag(Aff, r, k0 + 2, to_tf32(a.z + b.z));
        store_Afrag(Aff, r, k0 + 3, to_tf32(a.w + b.w));
    }
}

// 128x256x128 GEMM; warp (wr,wc) computes 32x64; acc[mi2][jn][c]
__device__ __forceinline__ void gemm_tile(const float* __restrict__ Aff,
                                          const float* __restrict__ Bff,
                                          int wr, int wc, int lane, float acc[2][8][4]) {
#pragma unroll
    for (int i = 0; i < 2; i++)
#pragma unroll
        for (int j = 0; j < 8; j++)
#pragma unroll
            for (int c = 0; c < 4; c++) acc[i][j][c] = 0.f;
#pragma unroll 4
    for (int ks = 0; ks < 16; ks++) {
        float4 a0 = *reinterpret_cast<const float4*>(Aff + (((wr * 2) * 16 + ks) * 32 + lane) * 4);
        float4 a1 = *reinterpret_cast<const float4*>(Aff + (((wr * 2 + 1) * 16 + ks) * 32 + lane) * 4);
#pragma unroll
        for (int p = 0; p < 4; p++) {
            float4 bv = *reinterpret_cast<const float4*>(Bff + (((wc * 4 + p) * 16 + ks) * 32 + lane) * 4);
            mma_tf32(acc[0][p * 2],     a0, bv.x, bv.y);
            mma_tf32(acc[0][p * 2 + 1], a0, bv.z, bv.w);
            mma_tf32(acc[1][p * 2],     a1, bv.x, bv.y);
            mma_tf32(acc[1][p * 2 + 1], a1, bv.z, bv.w);
        }
    }
}

__device__ __forceinline__ float grp_sum(float v) {
    v += __shfl_xor_sync(0xffffffffu, v, 1);
    v += __shfl_xor_sync(0xffffffffu, v, 2);
    return v;
}
__device__ __forceinline__ float grp_max(float v) {
    v = fmaxf(v, __shfl_xor_sync(0xffffffffu, v, 1));
    v = fmaxf(v, __shfl_xor_sync(0xffffffffu, v, 2));
    return v;
}

// ---------------- pass 1: U_K -> global max + raw column sums -------------------
__global__ void __launch_bounds__(NT, 1)
sp_kpass(const float* __restrict__ Kin, const float* __restrict__ omg, int ntiles) {
    extern __shared__ float sh[];
    float* Bff  = sh;
    float* Aff  = sh + BFF_F;
    float* hraw = Aff + AFF_F;            // 128
    float* hrow = hraw + MTILE;           // 128
    float* cs   = hrow + MTILE;           // 256
    unsigned* bmax = (unsigned*)(cs + NF);

    const int tid = threadIdx.x, wid = tid >> 5, lane = tid & 31;
    const int wr = wid >> 2, wc = wid & 3;

    load_B(omg, Bff, tid);
    if (tid < NF) cs[tid] = 0.f;
    if (tid == 0) *bmax = 0u;
    __syncthreads();

    float acc[2][8][4];
    for (int tile = blockIdx.x; tile < ntiles; tile += gridDim.x) {
        const size_t row0 = (size_t)tile * MTILE;
        if (tid < MTILE) hraw[tid] = 0.f;
        __syncthreads();
        load_A(Kin, row0, Aff, hraw, tid, true);
        __syncthreads();
        if (tid < MTILE) hrow[tid] = hraw[tid] * HC;
        __syncthreads();
        gemm_tile(Aff, Bff, wr, wc, lane, acc);

        float colp[16];
#pragma unroll
        for (int t = 0; t < 16; t++) colp[t] = 0.f;
        float lmax = -INFINITY;
#pragma unroll
        for (int mi2 = 0; mi2 < 2; mi2++)
#pragma unroll
            for (int h = 0; h < 2; h++) {
                const int r = wr * 32 + mi2 * 16 + (lane >> 2) + h * 8;
                const float hv = hrow[r];
#pragma unroll
                for (int jn = 0; jn < 8; jn++)
#pragma unroll
                    for (int cc = 0; cc < 2; cc++) {
                        const float u = acc[mi2][jn][h * 2 + cc];
                        lmax = fmaxf(lmax, u);
                        colp[jn * 2 + cc] += __expf(u - hv);
                    }
            }
#pragma unroll
        for (int t = 0; t < 16; t++) {
            float s = colp[t];
            s += __shfl_xor_sync(0xffffffffu, s, 4);
            s += __shfl_xor_sync(0xffffffffu, s, 8);
            s += __shfl_xor_sync(0xffffffffu, s, 16);
            colp[t] = s;
        }
        if (lane < 4) {
#pragma unroll
            for (int t = 0; t < 16; t++)
                atomicAdd(&cs[wc * 64 + (t >> 1) * 8 + 2 * lane + (t & 1)], colp[t]);
        }
#pragma unroll
        for (int o = 16; o; o >>= 1)
            lmax = fmaxf(lmax, __shfl_xor_sync(0xffffffffu, lmax, o));
        if (lane == 0) atomicMax(bmax, f2u(lmax));
        __syncthreads();
    }
    if (tid < NF) atomicAdd(&g_sumKraw[tid], cs[tid]);
    if (tid == 0) atomicMax(&g_max_u, *bmax);
}

// ---------------- pass 2: S1/S2/S3/T per row, scale V ---------------------------
__global__ void __launch_bounds__(NT, 1)
sp_final(const float* __restrict__ Qg, const float* __restrict__ Kg,
         const float* __restrict__ V, const float* __restrict__ omg,
         float* __restrict__ out, int ntiles) {
    extern __shared__ float sh[];
    float* Bff   = sh;
    float* Aff   = sh + BFF_F;
    float* red0  = Aff + AFF_F;        // 512
    float* red1  = red0 + 512;         // 512
    float* rowRM = red1 + 512;         // 128
    float* rowMS = rowRM + MTILE;      // 128
    float* rowS2 = rowMS + MTILE;      // 128
    float* rowS3 = rowS2 + MTILE;      // 128
    float* rowT  = rowS3 + MTILE;      // 128
    float* hraw  = rowT + MTILE;       // 128
    float* hq    = hraw + MTILE;       // 128
    float* hk    = hq + MTILE;         // 128
    float* sKs   = hk + MTILE;         // 256
    float* scal  = sKs + NF;           // 128
    float* ssum  = scal + MTILE;       // 1

    const int tid = threadIdx.x, wid = tid >> 5, lane = tid & 31;
    const int wr = wid >> 2, wc = wid & 3;
    const float gm = g_maxval;

    load_B(omg, Bff, tid);
    if (tid < NF) sKs[tid] = g_sumK[tid];
    __syncthreads();
    if (tid == 0) {
        float s = 0.f;
        for (int j = 0; j < NF; j++) s += sKs[j];
        *ssum = s;
    }
    __syncthreads();
    const float ssv = *ssum;

    float acc[2][8][4];
    for (int tile = blockIdx.x; tile < ntiles; tile += gridDim.x) {
        const size_t row0 = (size_t)tile * MTILE;

        // ======== Q phase ========
        if (tid < MTILE) hraw[tid] = 0.f;
        __syncthreads();
        load_A(Qg, row0, Aff, hraw, tid, true);
        __syncthreads();
        if (tid < MTILE) hq[tid] = hraw[tid] * HC;
        __syncthreads();
        gemm_tile(Aff, Bff, wr, wc, lane, acc);
        // row max (rm)
#pragma unroll
        for (int mi2 = 0; mi2 < 2; mi2++)
#pragma unroll
            for (int h = 0; h < 2; h++) {
                float m = -INFINITY;
#pragma unroll
                for (int jn = 0; jn < 8; jn++) {
                    m = fmaxf(m, acc[mi2][jn][h * 2]);
                    m = fmaxf(m, acc[mi2][jn][h * 2 + 1]);
                }
                m = grp_max(m);
                if ((lane & 3) == 0)
                    red0[(wr * 32 + mi2 * 16 + (lane >> 2) + h * 8) * 4 + wc] = m;
            }
        __syncthreads();
        if (tid < MTILE) {
            float4 m4 = *reinterpret_cast<float4*>(&red0[tid * 4]);
            rowRM[tid] = fmaxf(fmaxf(m4.x, m4.y), fmaxf(m4.z, m4.w));
        }
        __syncthreads();
        // S2, T
#pragma unroll
        for (int mi2 = 0; mi2 < 2; mi2++)
#pragma unroll
            for (int h = 0; h < 2; h++) {
                const int r = wr * 32 + mi2 * 16 + (lane >> 2) + h * 8;
                const float sub = hq[r] + rowRM[r];
                float s2 = 0.f, tt = 0.f;
#pragma unroll
                for (int jn = 0; jn < 8; jn++)
#pragma unroll
                    for (int cc = 0; cc < 2; cc++) {
                        const int col = wc * 64 + jn * 8 + 2 * (lane & 3) + cc;
                        const float e = __expf(acc[mi2][jn][h * 2 + cc] - sub);
                        s2 += e;
                        tt = fmaf(e, sKs[col], tt);
                    }
                s2 = grp_sum(s2); tt = grp_sum(tt);
                if ((lane & 3) == 0) { red0[r * 4 + wc] = s2; red1[r * 4 + wc] = tt; }
            }
        __syncthreads();
        if (tid < MTILE) {
            float4 a4 = *reinterpret_cast<float4*>(&red0[tid * 4]);
            float4 b4 = *reinterpret_cast<float4*>(&red1[tid * 4]);
            rowS2[tid] = a4.x + a4.y + a4.z + a4.w;
            rowT[tid]  = b4.x + b4.y + b4.z + b4.w;
            hraw[tid] = 0.f;
        }
        __syncthreads();

        // ======== K phase ========
        load_A(Kg, row0, Aff, hraw, tid, true);
        __syncthreads();
        if (tid < MTILE) hk[tid] = hraw[tid] * HC;
        __syncthreads();
        gemm_tile(Aff, Bff, wr, wc, lane, acc);
#pragma unroll
        for (int mi2 = 0; mi2 < 2; mi2++)
#pragma unroll
            for (int h = 0; h < 2; h++) {
                const int r = wr * 32 + mi2 * 16 + (lane >> 2) + h * 8;
                const float sub = hk[r] + gm;
                float s3 = 0.f;
#pragma unroll
                for (int jn = 0; jn < 8; jn++)
#pragma unroll
                    for (int cc = 0; cc < 2; cc++)
                        s3 += __expf(acc[mi2][jn][h * 2 + cc] - sub);
                s3 = grp_sum(s3);
                if ((lane & 3) == 0) red0[r * 4 + wc] = s3;
            }
        __syncthreads();
        if (tid < MTILE) {
            float4 a4 = *reinterpret_cast<float4*>(&red0[tid * 4]);
            rowS3[tid] = a4.x + a4.y + a4.z + a4.w;
        }
        __syncthreads();

        // ======== S = Q+K phase ========
        load_S(Qg, Kg, row0, Aff, tid);
        __syncthreads();
        gemm_tile(Aff, Bff, wr, wc, lane, acc);
#pragma unroll
        for (int mi2 = 0; mi2 < 2; mi2++)
#pragma unroll
            for (int h = 0; h < 2; h++) {
                float m = -INFINITY;
#pragma unroll
                for (int jn = 0; jn < 8; jn++) {
                    m = fmaxf(m, acc[mi2][jn][h * 2]);
                    m = fmaxf(m, acc[mi2][jn][h * 2 + 1]);
                }
                m = grp_max(m);
                if ((lane & 3) == 0)
                    red0[(wr * 32 + mi2 * 16 + (lane >> 2) + h * 8) * 4 + wc] = m;
            }
        __syncthreads();
        if (tid < MTILE) {
            float4 m4 = *reinterpret_cast<float4*>(&red0[tid * 4]);
            rowMS[tid] = fmaxf(fmaxf(m4.x, m4.y), fmaxf(m4.z, m4.w));
        }
        __syncthreads();
#pragma unroll
        for (int mi2 = 0; mi2 < 2; mi2++)
#pragma unroll
            for (int h = 0; h < 2; h++) {
                const int r = wr * 32 + mi2 * 16 + (lane >> 2) + h * 8;
                const float ms = rowMS[r];
                float s1 = 0.f;
#pragma unroll
                for (int jn = 0; jn < 8; jn++)
#pragma unroll
                    for (int cc = 0; cc < 2; cc++)
                        s1 += __expf(acc[mi2][jn][h * 2 + cc] - ms);
                s1 = grp_sum(s1);
                if ((lane & 3) == 0) red0[r * 4 + wc] = s1;
            }
        __syncthreads();
        if (tid < MTILE) {
            float4 a4 = *reinterpret_cast<float4*>(&red0[tid * 4]);
            const float sum1 = a4.x + a4.y + a4.z + a4.w;
            const float expo = rowMS[tid] - hq[tid] - hk[tid] - rowRM[tid] - gm;
            const float S1 = __expf(expo) * sum1;
            const float w = (S1 + 1e-4f * (rowS2[tid] + rowS3[tid]) + 2.56e-6f) * (1.f / 256.f);
            const float nm = (rowT[tid] + 1e-4f * ssv) * 0.0625f + 1e-8f;
            scal[tid] = w / nm;
        }
        __syncthreads();

        // ======== out = scal * V ========
        const float4* Vg = reinterpret_cast<const float4*>(V + row0 * KD);
        float4* Og = reinterpret_cast<float4*>(out + row0 * KD);
        for (int i = tid; i < MTILE * KD / 4; i += NT) {
            const float s = scal[i >> 5];
            float4 v = Vg[i];
            v.x *= s; v.y *= s; v.z *= s; v.w *= s;
            Og[i] = v;
        }
        __syncthreads();
    }
}

// --------------------------------- host -----------------------------------------
extern "C" void kernel_launch(void* const* d_in, const int* in_sizes, int n_in,
                              void* d_out, int out_size) {
    const float* Q   = (const float*)d_in[0];
    const float* K   = (const float*)d_in[1];
    const float* V   = (const float*)d_in[2];
    const float* omg = (const float*)d_in[3];
    float* out = (float*)d_out;

    const int N = in_sizes[0] / KD;
    const int ntiles = N / MTILE;

    int dev = 0, sms = 148;
    cudaGetDevice(&dev);
    cudaDeviceGetAttribute(&sms, cudaDevAttrMultiProcessorCount, dev);
    int grid = sms < ntiles ? sms : ntiles;

    const size_t smK = (size_t)(BFF_F + AFF_F + MTILE * 2 + NF + 4) * sizeof(float);
    const size_t smF = (size_t)(BFF_F + AFF_F + 1024 + MTILE * 8 + NF + MTILE + 8) * sizeof(float);
    cudaFuncSetAttribute(sp_kpass, cudaFuncAttributeMaxDynamicSharedMemorySize, (int)smK);
    cudaFuncSetAttribute(sp_final, cudaFuncAttributeMaxDynamicSharedMemorySize, (int)smF);

    sp_init<<<1, NF>>>();
    sp_kpass<<<grid, NT, smK>>>(K, omg, ntiles);
    sp_finalize<<<1, NF>>>((float)N * 1e-4f);
    sp_final<<<grid, NT, smF>>>(Q, K, V, omg, out, ntiles);
}

// round 5
// speedup vs baseline: 5.3400x; 3.5855x over previous
#include <cuda_runtime.h>
#include <cuda_fp16.h>
#include <math.h>
#include <stdint.h>

#define NT     512
#define MTILE  128
#define NF     256
#define KD     128
#define NMAX   262144

#define INVD4  0.2973017787506803f    // 128^(-1/4)
#define HC     0.04419417382415922f   // 1/(2*sqrt(128))

#define BFF_U32 16384                 // B fragments (fp16): 64 KB
#define AFF_U32 8192                  // A fragments (fp16): 32 KB

// ---------------- globals -------------------------------------------------------
static __device__ unsigned g_max_u;
static __device__ float    g_maxval;
static __device__ float    g_sumKraw[NF];
static __device__ float    g_sumK[NF];
static __device__ float    g_rowS3[NMAX];   // per-row sum exp(U_K - hk), unshifted

__device__ __forceinline__ unsigned f2u(float f) {
    unsigned b = __float_as_uint(f);
    return (b & 0x80000000u) ? ~b : (b | 0x80000000u);
}
__device__ __forceinline__ float u2f(unsigned u) {
    return (u & 0x80000000u) ? __uint_as_float(u ^ 0x80000000u) : __uint_as_float(~u);
}

__global__ void sp_init() {
    if (threadIdx.x == 0) g_max_u = 0u;
    g_sumKraw[threadIdx.x] = 0.f;
}
__global__ void sp_finalize(float neps) {
    const float gmax = u2f(g_max_u);
    if (threadIdx.x == 0) g_maxval = gmax;
    g_sumK[threadIdx.x] = (g_sumKraw[threadIdx.x] * expf(-gmax) + neps) * 0.0625f;
}

// ---------------- fp16 mma machinery --------------------------------------------
__device__ __forceinline__ void mma_f16(float* d, const uint4& a, uint32_t b0, uint32_t b1) {
    asm volatile(
        "mma.sync.aligned.m16n8k16.row.col.f32.f16.f16.f32 "
        "{%0,%1,%2,%3}, {%4,%5,%6,%7}, {%8,%9}, {%0,%1,%2,%3};\n"
        : "+f"(d[0]), "+f"(d[1]), "+f"(d[2]), "+f"(d[3])
        : "r"(a.x), "r"(a.y), "r"(a.z), "r"(a.w), "r"(b0), "r"(b1));
}

// load omega (scaled, fp16) into fragment-major B (one-time per kernel)
__device__ __forceinline__ void load_B_h(const float* __restrict__ omg,
                                         uint32_t* __restrict__ Bff, int tid) {
    __half* Bh = (__half*)Bff;
    for (int i = tid; i < KD * NF; i += NT) {
        const int k = i >> 8, n = i & 255;
        const __half hv = __float2half(omg[i] * INVD4);
        const int np = n >> 3, npair = np >> 1, ks = k >> 4;
        const int lane = ((n & 7) << 2) | ((k & 7) >> 1);
        const int slot = ((np & 1) << 1) | ((k >> 3) & 1);
        const int u32idx = ((npair * 8 + ks) * 32 + lane) * 4 + slot;
        Bh[u32idx * 2 + (k & 1)] = hv;
    }
}

// load X tile [128,128] fp32 -> fp16 fragments + exact per-row h (no atomics)
__device__ __forceinline__ void load_A_h(const float* __restrict__ X, size_t row0,
                                         uint32_t* __restrict__ Aff,
                                         float* __restrict__ hrow, int tid) {
    const int lane = tid & 31;
    const float4* g = (const float4*)(X + row0 * KD);
#pragma unroll
    for (int t = 0; t < MTILE * KD / 4 / NT; t++) {
        const int i = tid + t * NT;
        const int r = i >> 5, k0 = (i & 31) << 2;
        float4 v = g[i];
        float p = v.x * v.x + v.y * v.y + v.z * v.z + v.w * v.w;
#pragma unroll
        for (int o = 16; o; o >>= 1) p += __shfl_xor_sync(0xffffffffu, p, o);
        if (lane == 0) hrow[r] = p * HC;   // each warp-iteration covers exactly one row
        __half2 h01 = __floats2half2_rn(v.x, v.y);
        __half2 h23 = __floats2half2_rn(v.z, v.w);
        const int mi = r >> 4, rlo = r & 15, ks = k0 >> 4;
        const int reg = ((rlo >> 3) & 1) | (((k0 >> 3) & 1) << 1);
        const int ls  = ((rlo & 7) << 2) | ((k0 >> 1) & 3);
        uint32_t* base = Aff + (unsigned)((mi * 8 + ks) * 32) * 4 + reg;
        base[ls * 4]       = *(uint32_t*)&h01;
        base[(ls + 1) * 4] = *(uint32_t*)&h23;
    }
}

// 128x256x128 GEMM (fp16 in, fp32 acc); warp (wr,wc) owns 32x64; acc[mi2][jn][c]
__device__ __forceinline__ void gemm_tile(const uint4* __restrict__ Aff4,
                                          const uint4* __restrict__ Bff4,
                                          int wr, int wc, int lane,
                                          float acc[2][8][4], bool zero) {
    if (zero) {
#pragma unroll
        for (int i = 0; i < 2; i++)
#pragma unroll
            for (int j = 0; j < 8; j++)
#pragma unroll
                for (int c = 0; c < 4; c++) acc[i][j][c] = 0.f;
    }
#pragma unroll
    for (int ks = 0; ks < 8; ks++) {
        uint4 a0 = Aff4[((wr * 2) * 8 + ks) * 32 + lane];
        uint4 a1 = Aff4[((wr * 2 + 1) * 8 + ks) * 32 + lane];
#pragma unroll
        for (int p = 0; p < 4; p++) {
            uint4 bv = Bff4[((wc * 4 + p) * 8 + ks) * 32 + lane];
            mma_f16(acc[0][2 * p],     a0, bv.x, bv.y);
            mma_f16(acc[0][2 * p + 1], a0, bv.z, bv.w);
            mma_f16(acc[1][2 * p],     a1, bv.x, bv.y);
            mma_f16(acc[1][2 * p + 1], a1, bv.z, bv.w);
        }
    }
}

__device__ __forceinline__ float grp_sum(float v) {
    v += __shfl_xor_sync(0xffffffffu, v, 1);
    v += __shfl_xor_sync(0xffffffffu, v, 2);
    return v;
}
__device__ __forceinline__ float grp_max(float v) {
    v = fmaxf(v, __shfl_xor_sync(0xffffffffu, v, 1));
    v = fmaxf(v, __shfl_xor_sync(0xffffffffu, v, 2));
    return v;
}

// ---------------- pass 1: U_K -> gmax, colsums(exp), per-row S3raw --------------
__global__ void __launch_bounds__(NT, 1)
sp_kpass(const float* __restrict__ Kin, const float* __restrict__ omg, int ntiles) {
    extern __shared__ float sh[];
    uint32_t* Bff = (uint32_t*)sh;
    uint32_t* Aff = Bff + BFF_U32;
    float* hrow = (float*)(Aff + AFF_U32);   // 128
    float* cs   = hrow + MTILE;              // 256
    float* red  = cs + NF;                   // 512
    unsigned* bmax = (unsigned*)(red + 512);

    const int tid = threadIdx.x, wid = tid >> 5, lane = tid & 31;
    const int wr = wid >> 2, wc = wid & 3;

    load_B_h(omg, Bff, tid);
    if (tid < NF) cs[tid] = 0.f;
    if (tid == 0) *bmax = 0u;
    __syncthreads();

    float acc[2][8][4];
    for (int tile = blockIdx.x; tile < ntiles; tile += gridDim.x) {
        const size_t row0 = (size_t)tile * MTILE;
        load_A_h(Kin, row0, Aff, hrow, tid);
        __syncthreads();
        gemm_tile((const uint4*)Aff, (const uint4*)Bff, wr, wc, lane, acc, true);

        float colp[16];
#pragma unroll
        for (int t = 0; t < 16; t++) colp[t] = 0.f;
        float lmax = -INFINITY;
#pragma unroll
        for (int mi2 = 0; mi2 < 2; mi2++)
#pragma unroll
            for (int h = 0; h < 2; h++) {
                const int r = wr * 32 + mi2 * 16 + (lane >> 2) + h * 8;
                const float hv = hrow[r];
                float rs = 0.f;
#pragma unroll
                for (int jn = 0; jn < 8; jn++)
#pragma unroll
                    for (int cc = 0; cc < 2; cc++) {
                        const float u = acc[mi2][jn][h * 2 + cc];
                        lmax = fmaxf(lmax, u);
                        const float e = __expf(u - hv);
                        colp[jn * 2 + cc] += e;
                        rs += e;
                    }
                rs = grp_sum(rs);
                if ((lane & 3) == 0) red[r * 4 + wc] = rs;
            }
#pragma unroll
        for (int t = 0; t < 16; t++) {
            float s = colp[t];
            s += __shfl_xor_sync(0xffffffffu, s, 4);
            s += __shfl_xor_sync(0xffffffffu, s, 8);
            s += __shfl_xor_sync(0xffffffffu, s, 16);
            colp[t] = s;
        }
        if (lane < 4) {
#pragma unroll
            for (int t = 0; t < 16; t++)
                atomicAdd(&cs[wc * 64 + (t >> 1) * 8 + 2 * lane + (t & 1)], colp[t]);
        }
#pragma unroll
        for (int o = 16; o; o >>= 1)
            lmax = fmaxf(lmax, __shfl_xor_sync(0xffffffffu, lmax, o));
        if (lane == 0) atomicMax(bmax, f2u(lmax));
        __syncthreads();
        if (tid < MTILE)
            g_rowS3[row0 + tid] = red[tid * 4] + red[tid * 4 + 1] +
                                  red[tid * 4 + 2] + red[tid * 4 + 3];
        __syncthreads();
    }
    if (tid < NF) atomicAdd(&g_sumKraw[tid], cs[tid]);
    if (tid == 0) atomicMax(&g_max_u, *bmax);
}

// ---------------- pass 2: U_Q stats, then accumulate U_K -> U_S stats, scale V --
__global__ void __launch_bounds__(NT, 1)
sp_final(const float* __restrict__ Qg, const float* __restrict__ Kg,
         const float* __restrict__ V, const float* __restrict__ omg,
         float* __restrict__ out, int ntiles) {
    extern __shared__ float sh[];
    uint32_t* Bff = (uint32_t*)sh;
    uint32_t* Aff = Bff + BFF_U32;
    float* red0  = (float*)(Aff + AFF_U32);  // 512
    float* red1  = red0 + 512;               // 512
    float* rowRM = red1 + 512;               // 128
    float* rowMS = rowRM + MTILE;            // 128
    float* rowS2 = rowMS + MTILE;            // 128
    float* rowT  = rowS2 + MTILE;            // 128
    float* hq    = rowT + MTILE;             // 128
    float* hk    = hq + MTILE;               // 128
    float* sKs   = hk + MTILE;               // 256
    float* scal  = sKs + NF;                 // 128
    float* ssum  = scal + MTILE;             // 1

    const int tid = threadIdx.x, wid = tid >> 5, lane = tid & 31;
    const int wr = wid >> 2, wc = wid & 3;
    const float gm = g_maxval;
    const float expnegm = __expf(-gm);

    load_B_h(omg, Bff, tid);
    if (tid < NF) sKs[tid] = g_sumK[tid];
    __syncthreads();
    if (tid == 0) {
        float s = 0.f;
        for (int j = 0; j < NF; j++) s += sKs[j];
        *ssum = s;
    }
    __syncthreads();
    const float ssv = *ssum;

    float acc[2][8][4];
    for (int tile = blockIdx.x; tile < ntiles; tile += gridDim.x) {
        const size_t row0 = (size_t)tile * MTILE;

        // ======== Q phase: acc = U_Q ========
        load_A_h(Qg, row0, Aff, hq, tid);
        __syncthreads();
        gemm_tile((const uint4*)Aff, (const uint4*)Bff, wr, wc, lane, acc, true);
        // row max rm
#pragma unroll
        for (int mi2 = 0; mi2 < 2; mi2++)
#pragma unroll
            for (int h = 0; h < 2; h++) {
                float m = -INFINITY;
#pragma unroll
                for (int jn = 0; jn < 8; jn++) {
                    m = fmaxf(m, acc[mi2][jn][h * 2]);
                    m = fmaxf(m, acc[mi2][jn][h * 2 + 1]);
                }
                m = grp_max(m);
                if ((lane & 3) == 0)
                    red0[(wr * 32 + mi2 * 16 + (lane >> 2) + h * 8) * 4 + wc] = m;
            }
        __syncthreads();
        if (tid < MTILE) {
            float4 m4 = *(float4*)&red0[tid * 4];
            rowRM[tid] = fmaxf(fmaxf(m4.x, m4.y), fmaxf(m4.z, m4.w));
        }
        __syncthreads();
        // S2 = sum exp(U_Q - hq - rm); T = sum exp * sK
#pragma unroll
        for (int mi2 = 0; mi2 < 2; mi2++)
#pragma unroll
            for (int h = 0; h < 2; h++) {
                const int r = wr * 32 + mi2 * 16 + (lane >> 2) + h * 8;
                const float sub = hq[r] + rowRM[r];
                float s2 = 0.f, tt = 0.f;
#pragma unroll
                for (int jn = 0; jn < 8; jn++)
#pragma unroll
                    for (int cc = 0; cc < 2; cc++) {
                        const int col = wc * 64 + jn * 8 + 2 * (lane & 3) + cc;
                        const float e = __expf(acc[mi2][jn][h * 2 + cc] - sub);
                        s2 += e;
                        tt = fmaf(e, sKs[col], tt);
                    }
                s2 = grp_sum(s2); tt = grp_sum(tt);
                if ((lane & 3) == 0) { red0[r * 4 + wc] = s2; red1[r * 4 + wc] = tt; }
            }
        __syncthreads();
        if (tid < MTILE) {
            float4 a4 = *(float4*)&red0[tid * 4];
            float4 b4 = *(float4*)&red1[tid * 4];
            rowS2[tid] = a4.x + a4.y + a4.z + a4.w;
            rowT[tid]  = b4.x + b4.y + b4.z + b4.w;
        }
        __syncthreads();

        // ======== K phase: acc += U_K  (acc = U_S) ========
        load_A_h(Kg, row0, Aff, hk, tid);
        __syncthreads();
        gemm_tile((const uint4*)Aff, (const uint4*)Bff, wr, wc, lane, acc, false);
        // ms row max of U_S
#pragma unroll
        for (int mi2 = 0; mi2 < 2; mi2++)
#pragma unroll
            for (int h = 0; h < 2; h++) {
                float m = -INFINITY;
#pragma unroll
                for (int jn = 0; jn < 8; jn++) {
                    m = fmaxf(m, acc[mi2][jn][h * 2]);
                    m = fmaxf(m, acc[mi2][jn][h * 2 + 1]);
                }
                m = grp_max(m);
                if ((lane & 3) == 0)
                    red0[(wr * 32 + mi2 * 16 + (lane >> 2) + h * 8) * 4 + wc] = m;
            }
        __syncthreads();
        if (tid < MTILE) {
            float4 m4 = *(float4*)&red0[tid * 4];
            rowMS[tid] = fmaxf(fmaxf(m4.x, m4.y), fmaxf(m4.z, m4.w));
        }
        __syncthreads();
        // S1 = sum exp(U_S - ms)
#pragma unroll
        for (int mi2 = 0; mi2 < 2; mi2++)
#pragma unroll
            for (int h = 0; h < 2; h++) {
                const int r = wr * 32 + mi2 * 16 + (lane >> 2) + h * 8;
                const float ms = rowMS[r];
                float s1 = 0.f;
#pragma unroll
                for (int jn = 0; jn < 8; jn++)
#pragma unroll
                    for (int cc = 0; cc < 2; cc++)
                        s1 += __expf(acc[mi2][jn][h * 2 + cc] - ms);
                s1 = grp_sum(s1);
                if ((lane & 3) == 0) red0[r * 4 + wc] = s1;
            }
        __syncthreads();
        if (tid < MTILE) {
            float4 a4 = *(float4*)&red0[tid * 4];
            const float sum1 = a4.x + a4.y + a4.z + a4.w;
            const float S3 = g_rowS3[row0 + tid] * expnegm;
            const float expo = rowMS[tid] - hq[tid] - hk[tid] - rowRM[tid] - gm;
            const float S1 = __expf(expo) * sum1;
            const float w = (S1 + 1e-4f * (rowS2[tid] + S3) + 2.56e-6f) * (1.f / 256.f);
            const float nm = (rowT[tid] + 1e-4f * ssv) * 0.0625f + 1e-8f;
            scal[tid] = w / nm;
        }
        __syncthreads();

        // ======== out = scal * V ========
        const float4* Vg = (const float4*)(V + row0 * KD);
        float4* Og = (float4*)(out + row0 * KD);
#pragma unroll
        for (int t = 0; t < MTILE * KD / 4 / NT; t++) {
            const int i = tid + t * NT;
            const float s = scal[i >> 5];
            float4 v = Vg[i];
            v.x *= s; v.y *= s; v.z *= s; v.w *= s;
            Og[i] = v;
        }
        __syncthreads();
    }
}

// --------------------------------- host -----------------------------------------
extern "C" void kernel_launch(void* const* d_in, const int* in_sizes, int n_in,
                              void* d_out, int out_size) {
    const float* Q   = (const float*)d_in[0];
    const float* K   = (const float*)d_in[1];
    const float* V   = (const float*)d_in[2];
    const float* omg = (const float*)d_in[3];
    float* out = (float*)d_out;

    const int N = in_sizes[0] / KD;
    const int ntiles = N / MTILE;

    int dev = 0, sms = 148;
    cudaGetDevice(&dev);
    cudaDeviceGetAttribute(&sms, cudaDevAttrMultiProcessorCount, dev);
    int grid = sms < ntiles ? sms : ntiles;

    const size_t smK = (size_t)(BFF_U32 + AFF_U32) * 4 +
                       (size_t)(MTILE + NF + 512 + 4) * sizeof(float);
    const size_t smF = (size_t)(BFF_U32 + AFF_U32) * 4 +
                       (size_t)(512 * 2 + MTILE * 7 + NF + 8) * sizeof(float);
    cudaFuncSetAttribute(sp_kpass, cudaFuncAttributeMaxDynamicSharedMemorySize, (int)smK);
    cudaFuncSetAttribute(sp_final, cudaFuncAttributeMaxDynamicSharedMemorySize, (int)smF);

    sp_init<<<1, NF>>>();
    sp_kpass<<<grid, NT, smK>>>(K, omg, ntiles);
    sp_finalize<<<1, NF>>>((float)N * 1e-4f);
    sp_final<<<grid, NT, smF>>>(Q, K, V, omg, out, ntiles);
}

// round 6
// speedup vs baseline: 5.9419x; 1.1127x over previous
#include <cuda_runtime.h>
#include <cuda_fp16.h>
#include <math.h>
#include <stdint.h>

#define NT     256
#define MTILE  64
#define NF     256
#define KD     128
#define NMAX   262144

#define INVD4  0.2973017787506803f    // 128^(-1/4)
#define HC     0.04419417382415922f   // 1/(2*sqrt(128))

#define BFF_U32 16384                 // B fragments (fp16): 64 KB
#define AFF_U32 4096                  // A fragments (fp16): 16 KB (MTILE=64)

// ---------------- globals -------------------------------------------------------
static __device__ unsigned g_max_u;
static __device__ float    g_maxval;
static __device__ float    g_sumKraw[NF];
static __device__ float    g_sumK[NF];
static __device__ float    g_rowS3[NMAX];   // per-row sum exp(U_K - hk), unshifted

__device__ __forceinline__ unsigned f2u(float f) {
    unsigned b = __float_as_uint(f);
    return (b & 0x80000000u) ? ~b : (b | 0x80000000u);
}
__device__ __forceinline__ float u2f(unsigned u) {
    return (u & 0x80000000u) ? __uint_as_float(u ^ 0x80000000u) : __uint_as_float(~u);
}

__global__ void sp_init() {
    if (threadIdx.x == 0) g_max_u = 0u;
    g_sumKraw[threadIdx.x] = 0.f;
}
__global__ void sp_finalize(float neps) {
    const float gmax = u2f(g_max_u);
    if (threadIdx.x == 0) g_maxval = gmax;
    g_sumK[threadIdx.x] = (g_sumKraw[threadIdx.x] * expf(-gmax) + neps) * 0.0625f;
}

// ---------------- fp16 mma machinery --------------------------------------------
__device__ __forceinline__ void mma_f16(float* d, const uint4& a, uint32_t b0, uint32_t b1) {
    asm volatile(
        "mma.sync.aligned.m16n8k16.row.col.f32.f16.f16.f32 "
        "{%0,%1,%2,%3}, {%4,%5,%6,%7}, {%8,%9}, {%0,%1,%2,%3};\n"
        : "+f"(d[0]), "+f"(d[1]), "+f"(d[2]), "+f"(d[3])
        : "r"(a.x), "r"(a.y), "r"(a.z), "r"(a.w), "r"(b0), "r"(b1));
}

// load omega (scaled, fp16) into fragment-major B (one-time per kernel)
__device__ __forceinline__ void load_B_h(const float* __restrict__ omg,
                                         uint32_t* __restrict__ Bff, int tid) {
    __half* Bh = (__half*)Bff;
    for (int i = tid; i < KD * NF; i += NT) {
        const int k = i >> 8, n = i & 255;
        const __half hv = __float2half(omg[i] * INVD4);
        const int np = n >> 3, npair = np >> 1, ks = k >> 4;
        const int lane = ((n & 7) << 2) | ((k & 7) >> 1);
        const int slot = ((np & 1) << 1) | ((k >> 3) & 1);
        const int u32idx = ((npair * 8 + ks) * 32 + lane) * 4 + slot;
        Bh[u32idx * 2 + (k & 1)] = hv;
    }
}

// load X tile [64,128] fp32 -> fp16 fragments + exact per-row h (no atomics)
__device__ __forceinline__ void load_A_h(const float* __restrict__ X, size_t row0,
                                         uint32_t* __restrict__ Aff,
                                         float* __restrict__ hrow, int tid) {
    const int lane = tid & 31;
    const float4* g = (const float4*)(X + row0 * KD);
#pragma unroll
    for (int t = 0; t < MTILE * KD / 4 / NT; t++) {
        const int i = tid + t * NT;
        const int r = i >> 5, k0 = (i & 31) << 2;
        float4 v = g[i];
        float p = v.x * v.x + v.y * v.y + v.z * v.z + v.w * v.w;
#pragma unroll
        for (int o = 16; o; o >>= 1) p += __shfl_xor_sync(0xffffffffu, p, o);
        if (lane == 0) hrow[r] = p * HC;   // each warp-iteration covers exactly one row
        __half2 h01 = __floats2half2_rn(v.x, v.y);
        __half2 h23 = __floats2half2_rn(v.z, v.w);
        const int mi = r >> 4, rlo = r & 15, ks = k0 >> 4;
        const int reg = ((rlo >> 3) & 1) | (((k0 >> 3) & 1) << 1);
        const int ls  = ((rlo & 7) << 2) | ((k0 >> 1) & 3);
        uint32_t* base = Aff + (unsigned)((mi * 8 + ks) * 32) * 4 + reg;
        base[ls * 4]       = *(uint32_t*)&h01;
        base[(ls + 1) * 4] = *(uint32_t*)&h23;
    }
}

// 64x256x128 GEMM (fp16 in, fp32 acc); warp (wr,wc) owns 32x64; acc[mi2][jn][c]
__device__ __forceinline__ void gemm_tile(const uint4* __restrict__ Aff4,
                                          const uint4* __restrict__ Bff4,
                                          int wr, int wc, int lane,
                                          float acc[2][8][4], bool zero) {
    if (zero) {
#pragma unroll
        for (int i = 0; i < 2; i++)
#pragma unroll
            for (int j = 0; j < 8; j++)
#pragma unroll
                for (int c = 0; c < 4; c++) acc[i][j][c] = 0.f;
    }
#pragma unroll
    for (int ks = 0; ks < 8; ks++) {
        uint4 a0 = Aff4[((wr * 2) * 8 + ks) * 32 + lane];
        uint4 a1 = Aff4[((wr * 2 + 1) * 8 + ks) * 32 + lane];
#pragma unroll
        for (int p = 0; p < 4; p++) {
            uint4 bv = Bff4[((wc * 4 + p) * 8 + ks) * 32 + lane];
            mma_f16(acc[0][2 * p],     a0, bv.x, bv.y);
            mma_f16(acc[0][2 * p + 1], a0, bv.z, bv.w);
            mma_f16(acc[1][2 * p],     a1, bv.x, bv.y);
            mma_f16(acc[1][2 * p + 1], a1, bv.z, bv.w);
        }
    }
}

__device__ __forceinline__ float grp_sum(float v) {
    v += __shfl_xor_sync(0xffffffffu, v, 1);
    v += __shfl_xor_sync(0xffffffffu, v, 2);
    return v;
}
__device__ __forceinline__ float grp_max(float v) {
    v = fmaxf(v, __shfl_xor_sync(0xffffffffu, v, 1));
    v = fmaxf(v, __shfl_xor_sync(0xffffffffu, v, 2));
    return v;
}

// ---------------- pass 1: U_K -> gmax, colsums(exp), per-row S3raw --------------
__global__ void __launch_bounds__(NT, 2)
sp_kpass(const float* __restrict__ Kin, const float* __restrict__ omg, int ntiles) {
    extern __shared__ float sh[];
    uint32_t* Bff = (uint32_t*)sh;
    uint32_t* Aff = Bff + BFF_U32;
    float* hrow = (float*)(Aff + AFF_U32);   // 64
    float* cs   = hrow + MTILE;              // 256
    float* red  = cs + NF;                   // 256
    unsigned* bmax = (unsigned*)(red + MTILE * 4);

    const int tid = threadIdx.x, wid = tid >> 5, lane = tid & 31;
    const int wr = wid >> 2, wc = wid & 3;

    load_B_h(omg, Bff, tid);
    if (tid < NF) cs[tid] = 0.f;
    if (tid == 0) *bmax = 0u;
    __syncthreads();

    float acc[2][8][4];
    for (int tile = blockIdx.x; tile < ntiles; tile += gridDim.x) {
        const size_t row0 = (size_t)tile * MTILE;
        load_A_h(Kin, row0, Aff, hrow, tid);
        __syncthreads();
        gemm_tile((const uint4*)Aff, (const uint4*)Bff, wr, wc, lane, acc, true);

        float colp[16];
#pragma unroll
        for (int t = 0; t < 16; t++) colp[t] = 0.f;
        float lmax = -INFINITY;
#pragma unroll
        for (int mi2 = 0; mi2 < 2; mi2++)
#pragma unroll
            for (int h = 0; h < 2; h++) {
                const int r = wr * 32 + mi2 * 16 + (lane >> 2) + h * 8;
                const float hv = hrow[r];
                float rs = 0.f;
#pragma unroll
                for (int jn = 0; jn < 8; jn++)
#pragma unroll
                    for (int cc = 0; cc < 2; cc++) {
                        const float u = acc[mi2][jn][h * 2 + cc];
                        lmax = fmaxf(lmax, u);
                        const float e = __expf(u - hv);
                        colp[jn * 2 + cc] += e;
                        rs += e;
                    }
                rs = grp_sum(rs);
                if ((lane & 3) == 0) red[r * 4 + wc] = rs;
            }
#pragma unroll
        for (int t = 0; t < 16; t++) {
            float s = colp[t];
            s += __shfl_xor_sync(0xffffffffu, s, 4);
            s += __shfl_xor_sync(0xffffffffu, s, 8);
            s += __shfl_xor_sync(0xffffffffu, s, 16);
            colp[t] = s;
        }
        if (lane < 4) {
#pragma unroll
            for (int t = 0; t < 16; t++)
                atomicAdd(&cs[wc * 64 + (t >> 1) * 8 + 2 * lane + (t & 1)], colp[t]);
        }
#pragma unroll
        for (int o = 16; o; o >>= 1)
            lmax = fmaxf(lmax, __shfl_xor_sync(0xffffffffu, lmax, o));
        if (lane == 0) atomicMax(bmax, f2u(lmax));
        __syncthreads();
        if (tid < MTILE)
            g_rowS3[row0 + tid] = red[tid * 4] + red[tid * 4 + 1] +
                                  red[tid * 4 + 2] + red[tid * 4 + 3];
        __syncthreads();
    }
    if (tid < NF) atomicAdd(&g_sumKraw[tid], cs[tid]);
    if (tid == 0) atomicMax(&g_max_u, *bmax);
}

// ---------------- pass 2: U_Q stats, then accumulate U_K -> U_S stats, scale V --
__global__ void __launch_bounds__(NT, 2)
sp_final(const float* __restrict__ Qg, const float* __restrict__ Kg,
         const float* __restrict__ V, const float* __restrict__ omg,
         float* __restrict__ out, int ntiles) {
    extern __shared__ float sh[];
    uint32_t* Bff = (uint32_t*)sh;
    uint32_t* Aff = Bff + BFF_U32;
    float* red0  = (float*)(Aff + AFF_U32);  // 256
    float* red1  = red0 + MTILE * 4;         // 256
    float* rowRM = red1 + MTILE * 4;         // 64
    float* rowMS = rowRM + MTILE;            // 64
    float* rowS2 = rowMS + MTILE;            // 64
    float* rowT  = rowS2 + MTILE;            // 64
    float* hq    = rowT + MTILE;             // 64
    float* hk    = hq + MTILE;               // 64
    float* sKs   = hk + MTILE;               // 256
    float* scal  = sKs + NF;                 // 64
    float* ssum  = scal + MTILE;             // 1

    const int tid = threadIdx.x, wid = tid >> 5, lane = tid & 31;
    const int wr = wid >> 2, wc = wid & 3;
    const float gm = g_maxval;
    const float expnegm = __expf(-gm);

    load_B_h(omg, Bff, tid);
    if (tid < NF) sKs[tid] = g_sumK[tid];
    __syncthreads();
    if (tid == 0) {
        float s = 0.f;
        for (int j = 0; j < NF; j++) s += sKs[j];
        *ssum = s;
    }
    __syncthreads();
    const float ssv = *ssum;

    float acc[2][8][4];
    for (int tile = blockIdx.x; tile < ntiles; tile += gridDim.x) {
        const size_t row0 = (size_t)tile * MTILE;

        // ======== Q phase: acc = U_Q ========
        load_A_h(Qg, row0, Aff, hq, tid);
        __syncthreads();
        gemm_tile((const uint4*)Aff, (const uint4*)Bff, wr, wc, lane, acc, true);
        // row max rm
#pragma unroll
        for (int mi2 = 0; mi2 < 2; mi2++)
#pragma unroll
            for (int h = 0; h < 2; h++) {
                float m = -INFINITY;
#pragma unroll
                for (int jn = 0; jn < 8; jn++) {
                    m = fmaxf(m, acc[mi2][jn][h * 2]);
                    m = fmaxf(m, acc[mi2][jn][h * 2 + 1]);
                }
                m = grp_max(m);
                if ((lane & 3) == 0)
                    red0[(wr * 32 + mi2 * 16 + (lane >> 2) + h * 8) * 4 + wc] = m;
            }
        __syncthreads();
        if (tid < MTILE) {
            float4 m4 = *(float4*)&red0[tid * 4];
            rowRM[tid] = fmaxf(fmaxf(m4.x, m4.y), fmaxf(m4.z, m4.w));
        }
        __syncthreads();
        // S2 = sum exp(U_Q - hq - rm); T = sum exp * sK
#pragma unroll
        for (int mi2 = 0; mi2 < 2; mi2++)
#pragma unroll
            for (int h = 0; h < 2; h++) {
                const int r = wr * 32 + mi2 * 16 + (lane >> 2) + h * 8;
                const float sub = hq[r] + rowRM[r];
                float s2 = 0.f, tt = 0.f;
#pragma unroll
                for (int jn = 0; jn < 8; jn++)
#pragma unroll
                    for (int cc = 0; cc < 2; cc++) {
                        const int col = wc * 64 + jn * 8 + 2 * (lane & 3) + cc;
                        const float e = __expf(acc[mi2][jn][h * 2 + cc] - sub);
                        s2 += e;
                        tt = fmaf(e, sKs[col], tt);
                    }
                s2 = grp_sum(s2); tt = grp_sum(tt);
                if ((lane & 3) == 0) { red0[r * 4 + wc] = s2; red1[r * 4 + wc] = tt; }
            }
        __syncthreads();
        if (tid < MTILE) {
            float4 a4 = *(float4*)&red0[tid * 4];
            float4 b4 = *(float4*)&red1[tid * 4];
            rowS2[tid] = a4.x + a4.y + a4.z + a4.w;
            rowT[tid]  = b4.x + b4.y + b4.z + b4.w;
        }
        __syncthreads();

        // ======== K phase: acc += U_K  (acc = U_S) ========
        load_A_h(Kg, row0, Aff, hk, tid);
        __syncthreads();
        gemm_tile((const uint4*)Aff, (const uint4*)Bff, wr, wc, lane, acc, false);
        // ms row max of U_S
#pragma unroll
        for (int mi2 = 0; mi2 < 2; mi2++)
#pragma unroll
            for (int h = 0; h < 2; h++) {
                float m = -INFINITY;
#pragma unroll
                for (int jn = 0; jn < 8; jn++) {
                    m = fmaxf(m, acc[mi2][jn][h * 2]);
                    m = fmaxf(m, acc[mi2][jn][h * 2 + 1]);
                }
                m = grp_max(m);
                if ((lane & 3) == 0)
                    red0[(wr * 32 + mi2 * 16 + (lane >> 2) + h * 8) * 4 + wc] = m;
            }
        __syncthreads();
        if (tid < MTILE) {
            float4 m4 = *(float4*)&red0[tid * 4];
            rowMS[tid] = fmaxf(fmaxf(m4.x, m4.y), fmaxf(m4.z, m4.w));
        }
        __syncthreads();
        // S1 = sum exp(U_S - ms)
#pragma unroll
        for (int mi2 = 0; mi2 < 2; mi2++)
#pragma unroll
            for (int h = 0; h < 2; h++) {
                const int r = wr * 32 + mi2 * 16 + (lane >> 2) + h * 8;
                const float ms = rowMS[r];
                float s1 = 0.f;
#pragma unroll
                for (int jn = 0; jn < 8; jn++)
#pragma unroll
                    for (int cc = 0; cc < 2; cc++)
                        s1 += __expf(acc[mi2][jn][h * 2 + cc] - ms);
                s1 = grp_sum(s1);
                if ((lane & 3) == 0) red0[r * 4 + wc] = s1;
            }
        __syncthreads();
        if (tid < MTILE) {
            float4 a4 = *(float4*)&red0[tid * 4];
            const float sum1 = a4.x + a4.y + a4.z + a4.w;
            const float S3 = g_rowS3[row0 + tid] * expnegm;
            const float expo = rowMS[tid] - hq[tid] - hk[tid] - rowRM[tid] - gm;
            const float S1 = __expf(expo) * sum1;
            const float w = (S1 + 1e-4f * (rowS2[tid] + S3) + 2.56e-6f) * (1.f / 256.f);
            const float nm = (rowT[tid] + 1e-4f * ssv) * 0.0625f + 1e-8f;
            scal[tid] = w / nm;
        }
        __syncthreads();

        // ======== out = scal * V ========
        const float4* Vg = (const float4*)(V + row0 * KD);
        float4* Og = (float4*)(out + row0 * KD);
#pragma unroll
        for (int t = 0; t < MTILE * KD / 4 / NT; t++) {
            const int i = tid + t * NT;
            const float s = scal[i >> 5];
            float4 v = Vg[i];
            v.x *= s; v.y *= s; v.z *= s; v.w *= s;
            Og[i] = v;
        }
        __syncthreads();
    }
}

// --------------------------------- host -----------------------------------------
extern "C" void kernel_launch(void* const* d_in, const int* in_sizes, int n_in,
                              void* d_out, int out_size) {
    const float* Q   = (const float*)d_in[0];
    const float* K   = (const float*)d_in[1];
    const float* V   = (const float*)d_in[2];
    const float* omg = (const float*)d_in[3];
    float* out = (float*)d_out;

    const int N = in_sizes[0] / KD;
    const int ntiles = N / MTILE;

    int dev = 0, sms = 148;
    cudaGetDevice(&dev);
    cudaDeviceGetAttribute(&sms, cudaDevAttrMultiProcessorCount, dev);
    int grid = 2 * sms < ntiles ? 2 * sms : ntiles;

    const size_t smK = (size_t)(BFF_U32 + AFF_U32) * 4 +
                       (size_t)(MTILE + NF + MTILE * 4 + 4) * sizeof(float);
    const size_t smF = (size_t)(BFF_U32 + AFF_U32) * 4 +
                       (size_t)(MTILE * 4 * 2 + MTILE * 7 + NF + 8) * sizeof(float);
    cudaFuncSetAttribute(sp_kpass, cudaFuncAttributeMaxDynamicSharedMemorySize, (int)smK);
    cudaFuncSetAttribute(sp_final, cudaFuncAttributeMaxDynamicSharedMemorySize, (int)smF);

    sp_init<<<1, NF>>>();
    sp_kpass<<<grid, NT, smK>>>(K, omg, ntiles);
    sp_finalize<<<1, NF>>>((float)N * 1e-4f);
    sp_final<<<grid, NT, smF>>>(Q, K, V, omg, out, ntiles);
}